// round 13
// baseline (speedup 1.0000x reference)
#include <cuda_runtime.h>
#include <math.h>

#define D       256
#define PDY     258                     // padded rows (1-pixel zero border)
#define PDX     264                     // padded row width in float4; 264 ≡ 0 mod 8 (conflict-free)
#define NA      360
#define SR      16                      // strip rows owned per strip
#define NS      (D / SR)                // 16 strips
#define BROWS   (SR + 2)                // 18 buffer rows (padded rows k*SR .. k*SR+17)
#define STRIPF4 (BROWS * PDX)           // 4752 float4
#define ROWB    (PDX * 16)              // 4224 bytes per padded row
#define NTH     1024                    // 32 warps: TLP to fill LDS-latency gaps
#define PREPTH  512
#define SMEMB   (2 * STRIPF4 * 16)      // 152064 bytes (double buffer)

// Padded, pixel-major, 4-batch-packed images with zero border, row stride PDX.
// g_pad[0][g] : y-major  (padded row = y+1, col = x+1)
// g_pad[1][g] : x-major  (padded row = x+1, col = y+1)
__device__ float4 g_pad[2][2][PDY * PDX];
__device__ float2 g_cs[NA];

__global__ void radon_prep(const float* __restrict__ x) {
    int i  = blockIdx.x * PREPTH + threadIdx.x;
    int lg = blockIdx.y;                    // 0..3: layout = lg>>1, group = lg&1
    if (lg == 0 && i < NA) {
        double t = (double)i * (M_PI / 360.0);   // 0.5 deg steps
        g_cs[i] = make_float2((float)cos(t), (float)sin(t));
    }
    if (i >= PDY * PDX) return;
    int layout = lg >> 1, g = lg & 1;
    int pr = i / PDX, pc = i % PDX;
    float4 v = make_float4(0.f, 0.f, 0.f, 0.f);
    if (pr >= 1 && pr <= D && pc >= 1 && pc <= D) {
        int yy = layout ? (pc - 1) : (pr - 1);
        int xx = layout ? (pr - 1) : (pc - 1);
        const float* p = x + ((size_t)g * 4) * (D * D) + yy * D + xx;
        v = make_float4(p[0], p[D * D], p[2 * D * D], p[3 * D * D]);
    }
    g_pad[layout][g][i] = v;
}

// Strip k = padded rows [k*SR .. k*SR+17], contiguous block of 4752 float4.
__device__ __forceinline__ void strip_prefetch(const float4* __restrict__ src0,
                                               float4* buf, int tid) {
    const float4* s = src0 + tid;
    float4* d = buf + tid;
#pragma unroll
    for (int j = 0; j < 4; j++) {
        unsigned int da = (unsigned int)__cvta_generic_to_shared(d);
        asm volatile("cp.async.cg.shared.global [%0], [%1], 16;" :: "r"(da), "l"(s));
        s += NTH; d += NTH;
    }
    if (tid < STRIPF4 - 4 * NTH) {   // 4752 - 4096 = 656 leftovers
        unsigned int da = (unsigned int)__cvta_generic_to_shared(d);
        asm volatile("cp.async.cg.shared.global [%0], [%1], 16;" :: "r"(da), "l"(s));
    }
}

// CTA = (angle a, batch-group g). Thread (w ray, quarter q); q splits each h-range 4 ways.
// u = w-127.5, v = h-127.5:  ix = c*u - s*v + 127.5 ; iy = s*u + c*v + 127.5
// mode0 (|c|>=s): r=iy (rows), p=ix (cols), y-major layout.
// mode1 (s>|c|) : r=ix (rows), p=iy (cols), x-major layout.   |dr/dh| >= 0.707.
__global__ void __launch_bounds__(NTH, 1) radon_main(float* __restrict__ out) {
    extern __shared__ float4 sm[];
    const int a   = blockIdx.x;
    const int g   = blockIdx.y;
    const int tid = threadIdx.x;
    const int w   = tid & (D - 1);
    const int q   = tid >> 8;               // 0..3

    float2 cs = g_cs[a];
    float c = cs.x, s = cs.y;
    int   mode = (fabsf(c) >= s) ? 1 : 0;   // 1 => y-strip (layout 0)
    float r_u = mode ? s  : c;
    float r_v = mode ? c  : -s;
    float p_u = mode ? c  : s;
    float p_v = mode ? -s : c;
    const float4* __restrict__ base = g_pad[mode ? 0 : 1][g];

    float u    = (float)w - 127.5f;
    float A    = r_v;                                   // |A| >= 0.707
    float Bc   = fmaf(r_u, u, 127.5f * (1.0f - r_v));   // r(h) = A*h + Bc
    float Ap   = p_v;
    float Bp   = fmaf(p_u, u, 127.5f * (1.0f - p_v));   // p(h) = Ap*h + Bp
    float invA = 1.0f / A;
    float nBcInv = -Bc * invA;
    const float PMAXF = 255.99998f;                     // largest float < 256

    float ax = 0.0f, ay = 0.0f, az = 0.0f, aw = 0.0f;

    strip_prefetch(base, sm, tid);
    asm volatile("cp.async.commit_group;");

    for (int k = 0; k < NS; k++) {
        if (k + 1 < NS) {
            strip_prefetch(base + (k + 1) * SR * PDX, sm + ((k + 1) & 1) * STRIPF4, tid);
            asm volatile("cp.async.commit_group;");
            asm volatile("cp.async.wait_group 1;");
        } else {
            asm volatile("cp.async.wait_group 0;");
        }
        __syncthreads();
        const char* S = (const char*)(sm + (k & 1) * STRIPF4);

        const int lo    = k * SR;
        const int hi    = lo + SR - 1;
        const int loOwn = k ? lo : -1;          // strip 0 also owns floor(r) == -1
        const int span  = hi - loOwn;
        const int srMin = lo - 1;               // padded row 0
        const int srMax = lo + SR - 1;          // padded row 16; +1 row = 17 stays in buffer

        // widened h-range for floor(r) in [loOwn, hi]  <=>  r in [loOwn, hi+1)
        float e0 = fmaf((float)loOwn,    invA, nBcInv);
        float e1 = fmaf((float)(hi + 1), invA, nBcInv);
        float emin = fminf(e0, e1);
        float emax = fmaxf(e0, e1);
        int hbeg = max(0,     (int)floorf(emin) - 1);
        int hend = min(D - 1, (int)floorf(emax) + 1);
        int cnt  = hend - hbeg + 1; if (cnt < 0) cnt = 0;
        int ib   = (cnt * q) >> 2;
        int ie   = (cnt * (q + 1)) >> 2;

        // corner byte address = Cb + sr*ROWB + sp*16
        // (padded row = sr+1-lo in [0,16], padded col = sp+1 in [0,256]; +1 row/+1 col reads)
        const char* Cb = S + (size_t)(1 - lo) * ROWB + 16;
        float fh = (float)(hbeg + ib);

#pragma unroll 1
        for (int i = ib; i < ie; i++) {
            float rr = fmaf(A,  fh, Bc);        // exact per-iteration evaluation
            float pp = fmaf(Ap, fh, Bp);
            fh += 1.0f;
            pp = fminf(fmaxf(pp, -1.0f), PMAXF);
            float rfl = floorf(rr), pfl = floorf(pp);
            int sr = (int)rfl, sp = (int)pfl;
            float f = ((unsigned)(sr - loOwn) <= (unsigned)span) ? 1.0f : 0.0f;
            sr = min(max(sr, srMin), srMax);            // safe address even when f==0
            float wr1 = (rr - rfl) * f;
            float wr0 = f - wr1;
            float wp1 = pp - pfl, wp0 = 1.0f - wp1;

            const char* A0 = Cb + sr * ROWB + sp * 16;
            float4 v00 = *(const float4*)(A0);
            float4 v01 = *(const float4*)(A0 + 16);
            float4 v10 = *(const float4*)(A0 + ROWB);
            float4 v11 = *(const float4*)(A0 + ROWB + 16);

            float w00 = wr0 * wp0, w01 = wr0 * wp1;
            float w10 = wr1 * wp0, w11 = wr1 * wp1;
            ax += w00 * v00.x + w01 * v01.x + w10 * v10.x + w11 * v11.x;
            ay += w00 * v00.y + w01 * v01.y + w10 * v10.y + w11 * v11.y;
            az += w00 * v00.z + w01 * v01.z + w10 * v10.z + w11 * v11.z;
            aw += w00 * v00.w + w01 * v01.w + w10 * v10.w + w11 * v11.w;
        }
        __syncthreads();
    }

    // 4-way reduction via smem (loop ended with __syncthreads; buffer free)
    if (q) sm[(q - 1) * D + w] = make_float4(ax, ay, az, aw);
    __syncthreads();
    if (q == 0) {
        float4 o1 = sm[w];
        float4 o2 = sm[D + w];
        float4 o3 = sm[2 * D + w];
        ax += o1.x + o2.x + o3.x;
        ay += o1.y + o2.y + o3.y;
        az += o1.z + o2.z + o3.z;
        aw += o1.w + o2.w + o3.w;
        const float sc = 1.0f / 256.0f;
        int b0 = g * 4;
        out[((b0 + 0) * NA + a) * D + w] = ax * sc;
        out[((b0 + 1) * NA + a) * D + w] = ay * sc;
        out[((b0 + 2) * NA + a) * D + w] = az * sc;
        out[((b0 + 3) * NA + a) * D + w] = aw * sc;
    }
}

extern "C" void kernel_launch(void* const* d_in, const int* in_sizes, int n_in,
                              void* d_out, int out_size) {
    const float* x = (const float*)d_in[0];
    float* out = (float*)d_out;
    cudaFuncSetAttribute(radon_main, cudaFuncAttributeMaxDynamicSharedMemorySize, SMEMB);
    radon_prep<<<dim3((PDY * PDX + PREPTH - 1) / PREPTH, 4), PREPTH>>>(x);
    radon_main<<<dim3(NA, 2), NTH, SMEMB>>>(out);
}

// round 14
// speedup vs baseline: 1.5091x; 1.5091x over previous
#include <cuda_runtime.h>
#include <cuda_fp16.h>
#include <math.h>

#define D        256
#define PDY      258                    // padded rows (1-pixel zero border)
#define PDX      264                    // padded row width in pixels
#define NA       360
#define SR       16                     // strip rows owned per strip
#define NS       (D / SR)               // 16 strips
#define BROWS    (SR + 2)               // 18 buffer rows
#define STRIPPIX (BROWS * PDX)          // 4752 pixels (8B each)
#define STRIPU4  (STRIPPIX / 2)         // 2376 uint4 per strip buffer
#define ROWB     (PDX * 8)              // 2112 bytes per padded row
#define NTH      512
#define SMEMB    (2 * STRIPU4 * 16)     // 76032 bytes (double buffer)

// Padded, pixel-major images, 4 batches packed as half4 (uint2) per pixel.
// g_pad[0][g] : y-major  (padded row = y+1, col = x+1)
// g_pad[1][g] : x-major  (padded row = x+1, col = y+1)
__device__ uint2  g_pad[2][2][PDY * PDX];
__device__ float2 g_cs[NA];

__global__ void radon_prep(const float* __restrict__ x) {
    int i  = blockIdx.x * NTH + threadIdx.x;
    int lg = blockIdx.y;                    // 0..3: layout = lg>>1, group = lg&1
    if (lg == 0 && i < NA) {
        double t = (double)i * (M_PI / 360.0);   // 0.5 deg steps
        g_cs[i] = make_float2((float)cos(t), (float)sin(t));
    }
    if (i >= PDY * PDX) return;
    int layout = lg >> 1, g = lg & 1;
    int pr = i / PDX, pc = i % PDX;
    uint2 hv = make_uint2(0u, 0u);
    if (pr >= 1 && pr <= D && pc >= 1 && pc <= D) {
        int yy = layout ? (pc - 1) : (pr - 1);
        int xx = layout ? (pr - 1) : (pc - 1);
        const float* p = x + ((size_t)g * 4) * (D * D) + yy * D + xx;
        __half2 h01 = __floats2half2_rn(p[0],         p[D * D]);
        __half2 h23 = __floats2half2_rn(p[2 * D * D], p[3 * D * D]);
        hv.x = *(unsigned int*)&h01;
        hv.y = *(unsigned int*)&h23;
    }
    g_pad[layout][g][i] = hv;
}

// Strip k = padded rows [k*SR .. k*SR+17] = contiguous 2376 uint4.
__device__ __forceinline__ void strip_prefetch(const uint4* __restrict__ src0,
                                               uint4* buf, int tid) {
    const uint4* s = src0 + tid;
    uint4* d = buf + tid;
#pragma unroll
    for (int j = 0; j < 4; j++) {
        unsigned int da = (unsigned int)__cvta_generic_to_shared(d);
        asm volatile("cp.async.cg.shared.global [%0], [%1], 16;" :: "r"(da), "l"(s));
        s += NTH; d += NTH;
    }
    if (tid < STRIPU4 - 4 * NTH) {   // 2376 - 2048 = 328 leftovers
        unsigned int da = (unsigned int)__cvta_generic_to_shared(d);
        asm volatile("cp.async.cg.shared.global [%0], [%1], 16;" :: "r"(da), "l"(s));
    }
}

// CTA = (angle a, batch-group g). Thread (w ray, half); half splits each h-range.
// u = w-127.5, v = h-127.5:  ix = c*u - s*v + 127.5 ; iy = s*u + c*v + 127.5
// mode0 (|c|>=s): r=iy (rows), p=ix (cols), y-major layout.
// mode1 (s>|c|) : r=ix (rows), p=iy (cols), x-major layout.   |dr/dh| >= 0.707.
__global__ void __launch_bounds__(NTH, 2) radon_main(float* __restrict__ out) {
    extern __shared__ uint4 smv[];
    const int a    = blockIdx.x;
    const int g    = blockIdx.y;
    const int tid  = threadIdx.x;
    const int w    = tid & (D - 1);
    const int half = tid >> 8;

    float2 cs = g_cs[a];
    float c = cs.x, s = cs.y;
    int   mode = (fabsf(c) >= s) ? 1 : 0;   // 1 => y-strip (layout 0)
    float r_u = mode ? s  : c;
    float r_v = mode ? c  : -s;
    float p_u = mode ? c  : s;
    float p_v = mode ? -s : c;
    const uint4* __restrict__ base = (const uint4*)g_pad[mode ? 0 : 1][g];

    float u    = (float)w - 127.5f;
    float A    = r_v;                                   // |A| >= 0.707
    float Bc   = fmaf(r_u, u, 127.5f * (1.0f - r_v));   // r(h) = A*h + Bc
    float Ap   = p_v;
    float Bp   = fmaf(p_u, u, 127.5f * (1.0f - p_v));   // p(h) = Ap*h + Bp
    float invA = 1.0f / A;
    float nBcInv = -Bc * invA;
    const float PMAXF = 255.99998f;                     // largest float < 256

    float ax = 0.0f, ay = 0.0f, az = 0.0f, aw = 0.0f;

    strip_prefetch(base, smv, tid);
    asm volatile("cp.async.commit_group;");

    for (int k = 0; k < NS; k++) {
        if (k + 1 < NS) {
            strip_prefetch(base + (size_t)(k + 1) * SR * PDX / 2,
                           smv + ((k + 1) & 1) * STRIPU4, tid);
            asm volatile("cp.async.commit_group;");
            asm volatile("cp.async.wait_group 1;");
        } else {
            asm volatile("cp.async.wait_group 0;");
        }
        __syncthreads();
        const char* S = (const char*)(smv + (k & 1) * STRIPU4);

        const int lo    = k * SR;
        const int hi    = lo + SR - 1;
        const int loOwn = k ? lo : -1;          // strip 0 also owns floor(r) == -1
        const int span  = hi - loOwn;
        const int srMin = lo - 1;               // padded row 0
        const int srMax = lo + SR - 1;          // padded row 16; +1 row = 17 stays in buffer

        // widened h-range for floor(r) in [loOwn, hi]  <=>  r in [loOwn, hi+1)
        float e0 = fmaf((float)loOwn,    invA, nBcInv);
        float e1 = fmaf((float)(hi + 1), invA, nBcInv);
        float emin = fminf(e0, e1);
        float emax = fmaxf(e0, e1);
        int hbeg = max(0,     (int)floorf(emin) - 1);
        int hend = min(D - 1, (int)floorf(emax) + 1);
        int cnt  = hend - hbeg + 1; if (cnt < 0) cnt = 0;
        int ch   = (cnt + 1) >> 1;
        int ib   = half ? ch  : 0;
        int ie   = half ? cnt : ch;

        // corner byte address = Cb + sr*ROWB + sp*8
        // (padded row = sr+1-lo in [0,16], padded col = sp+1 in [0,256])
        const char* Cb = S + (size_t)(1 - lo) * ROWB + 8;
        float fh = (float)(hbeg + ib);

#pragma unroll 2
        for (int i = ib; i < ie; i++) {
            float rr = fmaf(A,  fh, Bc);        // exact per-iteration evaluation
            float pp = fmaf(Ap, fh, Bp);
            fh += 1.0f;
            pp = fminf(fmaxf(pp, -1.0f), PMAXF);
            float rfl = floorf(rr), pfl = floorf(pp);
            int sr = (int)rfl, sp = (int)pfl;
            float f = ((unsigned)(sr - loOwn) <= (unsigned)span) ? 1.0f : 0.0f;
            sr = min(max(sr, srMin), srMax);            // safe address even when f==0
            float wr1 = (rr - rfl) * f;                 // masked row weights
            float wr0 = f - wr1;
            float wp1 = pp - pfl, wp0 = 1.0f - wp1;

            const char* A0 = Cb + sr * ROWB + sp * 8;
            uint2 v00 = *(const uint2*)(A0);
            uint2 v01 = *(const uint2*)(A0 + 8);
            uint2 v10 = *(const uint2*)(A0 + ROWB);
            uint2 v11 = *(const uint2*)(A0 + ROWB + 8);

            __half2 hwp0 = __float2half2_rn(wp0);
            __half2 hwp1 = __float2half2_rn(wp1);
            __half2 hwr0 = __float2half2_rn(wr0);
            __half2 hwr1 = __float2half2_rn(wr1);

            __half2 c00a = *(__half2*)&v00.x, c00b = *(__half2*)&v00.y;
            __half2 c01a = *(__half2*)&v01.x, c01b = *(__half2*)&v01.y;
            __half2 c10a = *(__half2*)&v10.x, c10b = *(__half2*)&v10.y;
            __half2 c11a = *(__half2*)&v11.x, c11b = *(__half2*)&v11.y;

            __half2 t0a = __hfma2(c01a, hwp1, __hmul2(c00a, hwp0));
            __half2 t0b = __hfma2(c01b, hwp1, __hmul2(c00b, hwp0));
            __half2 t1a = __hfma2(c11a, hwp1, __hmul2(c10a, hwp0));
            __half2 t1b = __hfma2(c11b, hwp1, __hmul2(c10b, hwp0));
            __half2 ra  = __hfma2(t1a, hwr1, __hmul2(t0a, hwr0));
            __half2 rb  = __hfma2(t1b, hwr1, __hmul2(t0b, hwr0));

            float2 fa = __half22float2(ra);
            float2 fb = __half22float2(rb);
            ax += fa.x; ay += fa.y; az += fb.x; aw += fb.y;
        }
        __syncthreads();
    }

    // reduce the two halves via smem
    float4* red = (float4*)smv;
    if (half == 1) red[w] = make_float4(ax, ay, az, aw);
    __syncthreads();
    if (half == 0) {
        float4 o = red[w];
        ax += o.x; ay += o.y; az += o.z; aw += o.w;
        const float sc = 1.0f / 256.0f;
        int b0 = g * 4;
        out[((b0 + 0) * NA + a) * D + w] = ax * sc;
        out[((b0 + 1) * NA + a) * D + w] = ay * sc;
        out[((b0 + 2) * NA + a) * D + w] = az * sc;
        out[((b0 + 3) * NA + a) * D + w] = aw * sc;
    }
}

extern "C" void kernel_launch(void* const* d_in, const int* in_sizes, int n_in,
                              void* d_out, int out_size) {
    const float* x = (const float*)d_in[0];
    float* out = (float*)d_out;
    cudaFuncSetAttribute(radon_main, cudaFuncAttributeMaxDynamicSharedMemorySize, SMEMB);
    radon_prep<<<dim3((PDY * PDX + NTH - 1) / NTH, 4), NTH>>>(x);
    radon_main<<<dim3(NA, 2), NTH, SMEMB>>>(out);
}

// round 15
// speedup vs baseline: 1.7132x; 1.1353x over previous
#include <cuda_runtime.h>
#include <cuda_fp16.h>
#include <math.h>

#define D        256
#define PDY      258                    // padded rows (1-pixel zero border)
#define PDX      264                    // padded row width in pixels
#define NA       360
#define SR       16                     // strip rows owned per strip
#define NS       (D / SR)               // 16 strips
#define BROWS    (SR + 2)               // 18 buffer rows
#define STRIPPIX (BROWS * PDX)          // 4752 pixels (8B each)
#define STRIPU4  (STRIPPIX / 2)         // 2376 uint4 per strip buffer
#define ROWB     (PDX * 8)              // 2112 bytes per padded row
#define NTH      512
#define SMEMB    (2 * STRIPU4 * 16)     // 76032 bytes (double buffer)

// Padded, pixel-major images, 4 batches packed as half4 (uint2) per pixel.
// g_pad[0][g] : y-major  (padded row = y+1, col = x+1)
// g_pad[1][g] : x-major  (padded row = x+1, col = y+1)
__device__ uint2  g_pad[2][2][PDY * PDX];
__device__ float2 g_cs[NA];

__global__ void radon_prep(const float* __restrict__ x) {
    int i  = blockIdx.x * NTH + threadIdx.x;
    int lg = blockIdx.y;                    // 0..3: layout = lg>>1, group = lg&1
    if (lg == 0 && i < NA) {
        double t = (double)i * (M_PI / 360.0);   // 0.5 deg steps
        g_cs[i] = make_float2((float)cos(t), (float)sin(t));
    }
    if (i >= PDY * PDX) return;
    int layout = lg >> 1, g = lg & 1;
    int pr = i / PDX, pc = i % PDX;
    uint2 hv = make_uint2(0u, 0u);
    if (pr >= 1 && pr <= D && pc >= 1 && pc <= D) {
        int yy = layout ? (pc - 1) : (pr - 1);
        int xx = layout ? (pr - 1) : (pc - 1);
        const float* p = x + ((size_t)g * 4) * (D * D) + yy * D + xx;
        __half2 h01 = __floats2half2_rn(p[0],         p[D * D]);
        __half2 h23 = __floats2half2_rn(p[2 * D * D], p[3 * D * D]);
        hv.x = *(unsigned int*)&h01;
        hv.y = *(unsigned int*)&h23;
    }
    g_pad[layout][g][i] = hv;
}

// Strip k = padded rows [k*SR .. k*SR+17] = contiguous 2376 uint4.
__device__ __forceinline__ void strip_prefetch(const uint4* __restrict__ src0,
                                               uint4* buf, int tid) {
    const uint4* s = src0 + tid;
    uint4* d = buf + tid;
#pragma unroll
    for (int j = 0; j < 4; j++) {
        unsigned int da = (unsigned int)__cvta_generic_to_shared(d);
        asm volatile("cp.async.cg.shared.global [%0], [%1], 16;" :: "r"(da), "l"(s));
        s += NTH; d += NTH;
    }
    if (tid < STRIPU4 - 4 * NTH) {   // 2376 - 2048 = 328 leftovers
        unsigned int da = (unsigned int)__cvta_generic_to_shared(d);
        asm volatile("cp.async.cg.shared.global [%0], [%1], 16;" :: "r"(da), "l"(s));
    }
}

// CTA = (angle a, batch-group g). Thread (w ray, half); half splits each h-range.
// u = w-127.5, v = h-127.5:  ix = c*u - s*v + 127.5 ; iy = s*u + c*v + 127.5
// mode0 (|c|>=s): r=iy (rows), p=ix (cols), y-major layout.
// mode1 (s>|c|) : r=ix (rows), p=iy (cols), x-major layout.   |dr/dh| >= 0.707.
__global__ void __launch_bounds__(NTH, 2) radon_main(float* __restrict__ out) {
    extern __shared__ uint4 smv[];
    const int a    = blockIdx.x;
    const int g    = blockIdx.y;
    const int tid  = threadIdx.x;
    const int w    = tid & (D - 1);
    const int half = tid >> 8;

    float2 cs = g_cs[a];
    float c = cs.x, s = cs.y;
    int   mode = (fabsf(c) >= s) ? 1 : 0;   // 1 => y-strip (layout 0)
    float r_u = mode ? s  : c;
    float r_v = mode ? c  : -s;
    float p_u = mode ? c  : s;
    float p_v = mode ? -s : c;
    const uint4* __restrict__ base = (const uint4*)g_pad[mode ? 0 : 1][g];

    float u    = (float)w - 127.5f;
    float A    = r_v;                                   // |A| >= 0.707
    float Bc   = fmaf(r_u, u, 127.5f * (1.0f - r_v));   // r(h) = A*h + Bc
    float Ap   = p_v;
    float Bp   = fmaf(p_u, u, 127.5f * (1.0f - p_v));   // p(h) = Ap*h + Bp
    float invA = 1.0f / A;
    float nBcInv = -Bc * invA;
    const float PMAXF = 255.99998f;                     // largest float < 256
    const float MARG  = 0.002f;   // covers fp32 range-endpoint vs loop-fma discrepancy (<= 2e-4)

    float ax = 0.0f, ay = 0.0f, az = 0.0f, aw = 0.0f;

    strip_prefetch(base, smv, tid);
    asm volatile("cp.async.commit_group;");

    for (int k = 0; k < NS; k++) {
        if (k + 1 < NS) {
            strip_prefetch(base + (size_t)(k + 1) * SR * PDX / 2,
                           smv + ((k + 1) & 1) * STRIPU4, tid);
            asm volatile("cp.async.commit_group;");
            asm volatile("cp.async.wait_group 1;");
        } else {
            asm volatile("cp.async.wait_group 0;");
        }
        __syncthreads();
        const char* S = (const char*)(smv + (k & 1) * STRIPU4);

        const int lo    = k * SR;
        const int hi    = lo + SR - 1;
        const int loOwn = k ? lo : -1;          // strip 0 also owns floor(r) == -1
        const int span  = hi - loOwn;
        const int srMin = lo - 1;               // padded row 0
        const int srMax = lo + SR - 1;          // padded row 16; +1 row = 17 stays in buffer

        // tight h-range for floor(r) in [loOwn, hi]  <=>  r in [loOwn, hi+1);
        // MARG absorbs fp32 rounding; ownership mask adjudicates boundaries exactly.
        float e0 = fmaf((float)loOwn,    invA, nBcInv);
        float e1 = fmaf((float)(hi + 1), invA, nBcInv);
        float emin = fminf(e0, e1);
        float emax = fmaxf(e0, e1);
        int hbeg = max(0,     (int)ceilf(emin - MARG));
        int hend = min(D - 1, (int)floorf(emax + MARG));
        int cnt  = hend - hbeg + 1; if (cnt < 0) cnt = 0;
        int ch   = (cnt + 1) >> 1;
        int ib   = half ? ch  : 0;
        int ie   = half ? cnt : ch;

        // corner byte address = Cb + sr*ROWB + sp*8
        // (padded row = sr+1-lo in [0,16], padded col = sp+1 in [0,256])
        const char* Cb = S + (size_t)(1 - lo) * ROWB + 8;
        float fh = (float)(hbeg + ib);

#pragma unroll 2
        for (int i = ib; i < ie; i++) {
            float rr = fmaf(A,  fh, Bc);        // exact per-iteration evaluation
            float pp = fmaf(Ap, fh, Bp);
            fh += 1.0f;
            pp = fminf(fmaxf(pp, -1.0f), PMAXF);
            float rfl = floorf(rr), pfl = floorf(pp);
            int sr = (int)rfl, sp = (int)pfl;
            float f = ((unsigned)(sr - loOwn) <= (unsigned)span) ? 1.0f : 0.0f;
            sr = min(max(sr, srMin), srMax);            // safe address even when f==0
            float wr1 = (rr - rfl) * f;                 // masked row weights
            float wr0 = f - wr1;
            float wp1 = pp - pfl, wp0 = 1.0f - wp1;

            const char* A0 = Cb + sr * ROWB + sp * 8;
            uint2 v00 = *(const uint2*)(A0);
            uint2 v01 = *(const uint2*)(A0 + 8);
            uint2 v10 = *(const uint2*)(A0 + ROWB);
            uint2 v11 = *(const uint2*)(A0 + ROWB + 8);

            // packed weights; low/high splats fold into HFMA2 lane selectors
            __half2 hwp = __floats2half2_rn(wp0, wp1);
            __half2 hwr = __floats2half2_rn(wr0, wr1);
            __half2 wp0h = __low2half2(hwp),  wp1h = __high2half2(hwp);
            __half2 wr0h = __low2half2(hwr),  wr1h = __high2half2(hwr);

            __half2 c00a = *(__half2*)&v00.x, c00b = *(__half2*)&v00.y;
            __half2 c01a = *(__half2*)&v01.x, c01b = *(__half2*)&v01.y;
            __half2 c10a = *(__half2*)&v10.x, c10b = *(__half2*)&v10.y;
            __half2 c11a = *(__half2*)&v11.x, c11b = *(__half2*)&v11.y;

            __half2 t0a = __hfma2(c01a, wp1h, __hmul2(c00a, wp0h));
            __half2 t0b = __hfma2(c01b, wp1h, __hmul2(c00b, wp0h));
            __half2 t1a = __hfma2(c11a, wp1h, __hmul2(c10a, wp0h));
            __half2 t1b = __hfma2(c11b, wp1h, __hmul2(c10b, wp0h));
            __half2 ra  = __hfma2(t1a, wr1h, __hmul2(t0a, wr0h));
            __half2 rb  = __hfma2(t1b, wr1h, __hmul2(t0b, wr0h));

            float2 fa = __half22float2(ra);
            float2 fb = __half22float2(rb);
            ax += fa.x; ay += fa.y; az += fb.x; aw += fb.y;
        }
        __syncthreads();
    }

    // reduce the two halves via smem
    float4* red = (float4*)smv;
    if (half == 1) red[w] = make_float4(ax, ay, az, aw);
    __syncthreads();
    if (half == 0) {
        float4 o = red[w];
        ax += o.x; ay += o.y; az += o.z; aw += o.w;
        const float sc = 1.0f / 256.0f;
        int b0 = g * 4;
        out[((b0 + 0) * NA + a) * D + w] = ax * sc;
        out[((b0 + 1) * NA + a) * D + w] = ay * sc;
        out[((b0 + 2) * NA + a) * D + w] = az * sc;
        out[((b0 + 3) * NA + a) * D + w] = aw * sc;
    }
}

extern "C" void kernel_launch(void* const* d_in, const int* in_sizes, int n_in,
                              void* d_out, int out_size) {
    const float* x = (const float*)d_in[0];
    float* out = (float*)d_out;
    cudaFuncSetAttribute(radon_main, cudaFuncAttributeMaxDynamicSharedMemorySize, SMEMB);
    radon_prep<<<dim3((PDY * PDX + NTH - 1) / NTH, 4), NTH>>>(x);
    radon_main<<<dim3(NA, 2), NTH, SMEMB>>>(out);
}